// round 4
// baseline (speedup 1.0000x reference)
#include <cuda_runtime.h>
#include <cuda_bf16.h>
#include <stdint.h>
#include <math.h>

#define BATCH 2048
#define NTOK 98
#define DIM 128
#define HEADS 4
#define NWIN 256
#define NN (NTOK * NTOK)   // 9604
#define MTOT (BATCH * NTOK)  // 200704

// Scratch (device globals)
__device__ __nv_bfloat16 g_qh[(size_t)MTOT * 384];   // qkv hi plane
__device__ __nv_bfloat16 g_ql[(size_t)MTOT * 384];   // qkv lo plane
__device__ __nv_bfloat16 g_oh[(size_t)MTOT * 128];   // attn-out hi plane
__device__ __nv_bfloat16 g_ol[(size_t)MTOT * 128];   // attn-out lo plane
__device__ __nv_bfloat16 g_sbm[(size_t)NWIN * HEADS * NN];  // bias+mask bf16

// ===========================================================================
__device__ __forceinline__ uint32_t smem_u32(const void* p) {
    uint32_t a;
    asm("{ .reg .u64 t; cvta.to.shared.u64 t, %1; cvt.u32.u64 %0, t; }" : "=r"(a) : "l"(p));
    return a;
}
__device__ __forceinline__ void ldsm_x4(uint32_t* r, uint32_t addr) {
    asm volatile("ldmatrix.sync.aligned.m8n8.x4.shared.b16 {%0,%1,%2,%3}, [%4];"
                 : "=r"(r[0]), "=r"(r[1]), "=r"(r[2]), "=r"(r[3]) : "r"(addr));
}
__device__ __forceinline__ void ldsm_x2(uint32_t* r, uint32_t addr) {
    asm volatile("ldmatrix.sync.aligned.m8n8.x2.shared.b16 {%0,%1}, [%2];"
                 : "=r"(r[0]), "=r"(r[1]) : "r"(addr));
}
__device__ __forceinline__ void ldsm_x2t(uint32_t* r, uint32_t addr) {
    asm volatile("ldmatrix.sync.aligned.m8n8.x2.trans.shared.b16 {%0,%1}, [%2];"
                 : "=r"(r[0]), "=r"(r[1]) : "r"(addr));
}
__device__ __forceinline__ void mma_bf16(float* d, const uint32_t* a, const uint32_t* b) {
    asm volatile("mma.sync.aligned.m16n8k16.row.col.f32.bf16.bf16.f32 "
                 "{%0,%1,%2,%3}, {%4,%5,%6,%7}, {%8,%9}, {%0,%1,%2,%3};"
                 : "+f"(d[0]), "+f"(d[1]), "+f"(d[2]), "+f"(d[3])
                 : "r"(a[0]), "r"(a[1]), "r"(a[2]), "r"(a[3]), "r"(b[0]), "r"(b[1]));
}
__device__ __forceinline__ uint32_t packbf(float a, float b) {
    __nv_bfloat162 t = __float22bfloat162_rn(make_float2(a, b));
    return *(uint32_t*)&t;
}
__device__ __forceinline__ float lopart(float v) {
    return v - __bfloat162float(__float2bfloat16(v));
}
__device__ __forceinline__ void split4(float4 v, uint2& hi, uint2& lo) {
    __nv_bfloat16 hx = __float2bfloat16(v.x), hy = __float2bfloat16(v.y);
    __nv_bfloat16 hz = __float2bfloat16(v.z), hw = __float2bfloat16(v.w);
    __nv_bfloat162 h0 = __halves2bfloat162(hx, hy), h1 = __halves2bfloat162(hz, hw);
    hi.x = *(uint32_t*)&h0; hi.y = *(uint32_t*)&h1;
    lo.x = packbf(v.x - __bfloat162float(hx), v.y - __bfloat162float(hy));
    lo.y = packbf(v.z - __bfloat162float(hz), v.w - __bfloat162float(hw));
}
__device__ __forceinline__ void split2(float a, float b, uint32_t& hi, uint32_t& lo) {
    __nv_bfloat16 ha = __float2bfloat16(a), hb = __float2bfloat16(b);
    __nv_bfloat162 hh = __halves2bfloat162(ha, hb);
    hi = *(uint32_t*)&hh;
    lo = packbf(a - __bfloat162float(ha), b - __bfloat162float(hb));
}
// swizzled smem address: 256B-pitch rows, XOR 16B-chunk by row&7
__device__ __forceinline__ uint32_t swz(uint32_t r, uint32_t cb) {
    return (r << 8) + (cb ^ ((r & 7) << 4));
}

// ===========================================================================
// bias+mask combine
// ===========================================================================
__global__ void build_sbm_kernel(const float* __restrict__ table,
                                 const int* __restrict__ rel,
                                 const float* __restrict__ mask) {
    int nm = blockIdx.x * 256 + threadIdx.x;
    int wh = blockIdx.y;
    if (nm < NN) {
        int w = wh >> 2, h = wh & 3;
        float v = table[rel[nm] * HEADS + h] + mask[(size_t)w * NN + nm];
        g_sbm[(size_t)wh * NN + nm] = __float2bfloat16(v);
    }
}

// ===========================================================================
// HMMA GEMM: C[M][N] = A[M][128] @ W[N][128]^T + bias  (bf16 hi/lo 3-pass)
// Block 64M x 128N, 256 threads (8 warps, warp tile 32x32). K=128 resident.
// IN_SPLIT: A arrives as bf16 hi/lo planes; else fp32 (split inline).
// OUT_SPLIT: write bf16 hi/lo planes; else fp32.
// ===========================================================================
#define GEMM_SMEM 98304
#define AH_OFF 0
#define AL_OFF 16384
#define WH_OFF 32768
#define WL_OFF 65536

template<int IN_SPLIT, int OUT_SPLIT>
__global__ __launch_bounds__(256, 2) void gemm_hmma(
    const float* __restrict__ Af,
    const __nv_bfloat16* __restrict__ Ahg, const __nv_bfloat16* __restrict__ Alg,
    const float* __restrict__ W, const float* __restrict__ bias,
    float* __restrict__ Cf, uint32_t* __restrict__ Ch, uint32_t* __restrict__ Cl,
    int N)
{
    extern __shared__ char sm[];
    const uint32_t smb = smem_u32(sm);
    const int tid = threadIdx.x;
    const int wid = tid >> 5, lane = tid & 31;
    const size_t m0 = (size_t)blockIdx.x * 64;
    const int n0 = blockIdx.y * 128;

    // ---- stage A (64 rows x 128 cols) ----
    if (IN_SPLIT) {
#pragma unroll
        for (int i = 0; i < 4; i++) {
            int idx = tid + 256 * i;           // 1024 = 64 rows * 16 chunks
            int r = idx >> 4;
            uint32_t cb = (uint32_t)(idx & 15) << 4;
            const char* bh = (const char*)(Ahg + (m0 + r) * 128);
            const char* bl = (const char*)(Alg + (m0 + r) * 128);
            *(uint4*)(sm + AH_OFF + swz(r, cb)) = *(const uint4*)(bh + cb);
            *(uint4*)(sm + AL_OFF + swz(r, cb)) = *(const uint4*)(bl + cb);
        }
    } else {
#pragma unroll
        for (int i = 0; i < 8; i++) {
            int idx = tid + 256 * i;           // 2048 = 64 rows * 32 float4
            int r = idx >> 5;
            int c4 = (idx & 31) << 2;
            float4 v = *(const float4*)(Af + (m0 + r) * 128 + c4);
            uint2 hi, lo;
            split4(v, hi, lo);
            *(uint2*)(sm + AH_OFF + swz(r, c4 * 2)) = hi;
            *(uint2*)(sm + AL_OFF + swz(r, c4 * 2)) = lo;
        }
    }
    // ---- stage W (128 rows x 128 cols, fp32 -> hi/lo) ----
#pragma unroll
    for (int i = 0; i < 16; i++) {
        int idx = tid + 256 * i;               // 4096
        int r = idx >> 5;
        int c4 = (idx & 31) << 2;
        float4 v = *(const float4*)(W + (size_t)(n0 + r) * 128 + c4);
        uint2 hi, lo;
        split4(v, hi, lo);
        *(uint2*)(sm + WH_OFF + swz(r, c4 * 2)) = hi;
        *(uint2*)(sm + WL_OFF + swz(r, c4 * 2)) = lo;
    }
    __syncthreads();

    const int wm = (wid & 1) * 32;
    const int wn = (wid >> 1) * 32;

    float acc[2][4][4];
#pragma unroll
    for (int mi = 0; mi < 2; mi++)
#pragma unroll
        for (int ni = 0; ni < 4; ni++)
#pragma unroll
            for (int c = 0; c < 4; c++) acc[mi][ni][c] = 0.f;

#pragma unroll
    for (int kc = 0; kc < 8; kc++) {
        uint32_t cb = (uint32_t)(kc * 32 + ((lane >> 4) & 1) * 16);
        uint32_t ah[2][4], al[2][4], bh[2][4], bl[2][4];
#pragma unroll
        for (int mi = 0; mi < 2; mi++) {
            uint32_t r = (uint32_t)(wm + mi * 16 + (lane & 15));
            ldsm_x4(ah[mi], smb + AH_OFF + swz(r, cb));
            ldsm_x4(al[mi], smb + AL_OFF + swz(r, cb));
        }
#pragma unroll
        for (int g = 0; g < 2; g++) {
            uint32_t r = (uint32_t)(wn + g * 16 + (lane & 15));
            ldsm_x4(bh[g], smb + WH_OFF + swz(r, cb));
            ldsm_x4(bl[g], smb + WL_OFF + swz(r, cb));
        }
#pragma unroll
        for (int mi = 0; mi < 2; mi++)
#pragma unroll
            for (int ni = 0; ni < 4; ni++) {
                int g = ni >> 1, hf = ni & 1;
                uint32_t B0[2]  = {bh[g][hf], bh[g][hf + 2]};
                uint32_t Bl0[2] = {bl[g][hf], bl[g][hf + 2]};
                mma_bf16(acc[mi][ni], ah[mi], B0);
                mma_bf16(acc[mi][ni], al[mi], B0);
                mma_bf16(acc[mi][ni], ah[mi], Bl0);
            }
    }

    // ---- epilogue ----
    const int rq = lane >> 2, cq = (lane & 3) * 2;
#pragma unroll
    for (int mi = 0; mi < 2; mi++) {
        size_t rA = m0 + wm + mi * 16 + rq;
        size_t rB = rA + 8;
#pragma unroll
        for (int ni = 0; ni < 4; ni++) {
            int col = n0 + wn + ni * 8 + cq;
            float b0 = bias[col], b1 = bias[col + 1];
            float v0 = acc[mi][ni][0] + b0, v1 = acc[mi][ni][1] + b1;
            float v2 = acc[mi][ni][2] + b0, v3 = acc[mi][ni][3] + b1;
            if (OUT_SPLIT) {
                uint32_t hi, lo;
                split2(v0, v1, hi, lo);
                Ch[(rA * N + col) >> 1] = hi;
                Cl[(rA * N + col) >> 1] = lo;
                split2(v2, v3, hi, lo);
                Ch[(rB * N + col) >> 1] = hi;
                Cl[(rB * N + col) >> 1] = lo;
            } else {
                *(float2*)(Cf + rA * N + col) = make_float2(v0, v1);
                *(float2*)(Cf + rB * N + col) = make_float2(v2, v3);
            }
        }
    }
}

// ===========================================================================
// HMMA attention: one CTA per (window, head), 128 threads (4 warps).
// Reads qkv hi/lo bf16 planes; writes attn-out hi/lo planes.
// Scale folded into softmax (S*scale + bias).
// ===========================================================================
#define PITCH 80
#define QH_OFF 0
#define QL_OFF 10240
#define KH_OFF 20480
#define KL_OFF 29440
#define VH_OFF 38400
#define VL_OFF 47360
#define SB_OFF 56320
#define ATTN_SMEM 75584

__global__ __launch_bounds__(128) void attn_hmma_kernel() {
    extern __shared__ char smraw[];
    const uint32_t smb = smem_u32(smraw);
    char* sm = smraw;

    const int b = blockIdx.x, h = blockIdx.y;
    const int tid = threadIdx.x;
    const int wid = tid >> 5, lane = tid & 31;

    // zero operand tiles (pads must be exactly 0)
    {
        float4 z = make_float4(0.f, 0.f, 0.f, 0.f);
        float4* p = (float4*)sm;
#pragma unroll
        for (int i = 0; i < 28; i++) {
            int idx = tid + 128 * i;
            if (idx < 3520) p[idx] = z;
        }
    }
    __syncthreads();

    // copy q/k/v hi+lo planes into pitch-80 smem tiles (pure uint4 copies)
    for (int idx = tid; idx < NTOK * 4; idx += 128) {
        int n = idx >> 2;
        int c = (idx & 3) * 8;                      // element offset in 32-wide
        size_t gr = ((size_t)b * NTOK + n) * 384 + h * 32 + c;
        uint32_t off = (uint32_t)(n * PITCH + c * 2);
        *(uint4*)(sm + QH_OFF + off) = *(const uint4*)(g_qh + gr);
        *(uint4*)(sm + QL_OFF + off) = *(const uint4*)(g_ql + gr);
        *(uint4*)(sm + KH_OFF + off) = *(const uint4*)(g_qh + gr + 128);
        *(uint4*)(sm + KL_OFF + off) = *(const uint4*)(g_ql + gr + 128);
        *(uint4*)(sm + VH_OFF + off) = *(const uint4*)(g_qh + gr + 256);
        *(uint4*)(sm + VL_OFF + off) = *(const uint4*)(g_ql + gr + 256);
    }
    // stage bias+mask tile
    {
        const uint32_t* src = (const uint32_t*)(g_sbm + ((size_t)((b & (NWIN - 1)) * HEADS + h)) * NN);
        uint32_t* dst = (uint32_t*)(sm + SB_OFF);
        for (int i = tid; i < NN / 2; i += 128) dst[i] = src[i];
    }
    __syncthreads();

    const int l8 = lane & 7;
    const int rq = lane >> 2;
    const int cq = (lane & 3) * 2;

    // ---- S = QK^T, 3 passes ----
    float acc[2][13][4];
#pragma unroll
    for (int mi = 0; mi < 2; mi++)
#pragma unroll
        for (int nt = 0; nt < 13; nt++)
#pragma unroll
            for (int c = 0; c < 4; c++) acc[mi][nt][c] = 0.f;

    uint32_t qbase[3] = {smb + QH_OFF, smb + QH_OFF, smb + QL_OFF};
    uint32_t kbase[3] = {smb + KH_OFF, smb + KL_OFF, smb + KH_OFF};

#pragma unroll 1
    for (int p = 0; p < 3; p++) {
        uint32_t qb = qbase[p], kb = kbase[p];
#pragma unroll
        for (int kc = 0; kc < 2; kc++) {
            int sel = lane >> 3;
            uint32_t arow = (uint32_t)(wid * 32 + (sel & 1) * 8 + l8);
            uint32_t aoff = (uint32_t)(kc * 32 + (sel >> 1) * 16);
            uint32_t a0[4], a1[4];
            ldsm_x4(a0, qb + arow * PITCH + aoff);
            ldsm_x4(a1, qb + (arow + 16) * PITCH + aoff);
            uint32_t boff = (uint32_t)(kc * 32 + ((lane >> 3) & 1) * 16);
#pragma unroll
            for (int nt = 0; nt < 13; nt++) {
                uint32_t bf[2];
                ldsm_x2(bf, kb + (uint32_t)(nt * 8 + l8) * PITCH + boff);
                mma_bf16(acc[0][nt], a0, bf);
                mma_bf16(acc[1][nt], a1, bf);
            }
        }
    }

    // ---- scale*S + bias+mask, softmax ----
    const float scale = 0.17677669529663687f;
    float sumA[2], sumB[2];
#pragma unroll
    for (int mi = 0; mi < 2; mi++) {
        int rA = wid * 32 + mi * 16 + rq;
        int rB = rA + 8;
        float mxA = -1e30f, mxB = -1e30f;
#pragma unroll
        for (int nt = 0; nt < 13; nt++) {
            int col = nt * 8 + cq;
            if (col < 98) {
                if (rA < 98) {
                    uint32_t u = *(const uint32_t*)(sm + SB_OFF + rA * 196 + col * 2);
                    __nv_bfloat162 bb = *(__nv_bfloat162*)&u;
                    acc[mi][nt][0] = fmaf(acc[mi][nt][0], scale, __bfloat162float(bb.x));
                    acc[mi][nt][1] = fmaf(acc[mi][nt][1], scale, __bfloat162float(bb.y));
                }
                if (rB < 98) {
                    uint32_t u = *(const uint32_t*)(sm + SB_OFF + rB * 196 + col * 2);
                    __nv_bfloat162 bb = *(__nv_bfloat162*)&u;
                    acc[mi][nt][2] = fmaf(acc[mi][nt][2], scale, __bfloat162float(bb.x));
                    acc[mi][nt][3] = fmaf(acc[mi][nt][3], scale, __bfloat162float(bb.y));
                }
            } else {
                acc[mi][nt][0] = -1e30f; acc[mi][nt][1] = -1e30f;
                acc[mi][nt][2] = -1e30f; acc[mi][nt][3] = -1e30f;
            }
            mxA = fmaxf(mxA, fmaxf(acc[mi][nt][0], acc[mi][nt][1]));
            mxB = fmaxf(mxB, fmaxf(acc[mi][nt][2], acc[mi][nt][3]));
        }
        mxA = fmaxf(mxA, __shfl_xor_sync(0xffffffffu, mxA, 1));
        mxA = fmaxf(mxA, __shfl_xor_sync(0xffffffffu, mxA, 2));
        mxB = fmaxf(mxB, __shfl_xor_sync(0xffffffffu, mxB, 1));
        mxB = fmaxf(mxB, __shfl_xor_sync(0xffffffffu, mxB, 2));
        float sA = 0.f, sB = 0.f;
#pragma unroll
        for (int nt = 0; nt < 13; nt++) {
            float e0 = __expf(acc[mi][nt][0] - mxA);
            float e1 = __expf(acc[mi][nt][1] - mxA);
            float e2 = __expf(acc[mi][nt][2] - mxB);
            float e3 = __expf(acc[mi][nt][3] - mxB);
            acc[mi][nt][0] = e0; acc[mi][nt][1] = e1;
            acc[mi][nt][2] = e2; acc[mi][nt][3] = e3;
            sA += e0 + e1; sB += e2 + e3;
        }
        sA += __shfl_xor_sync(0xffffffffu, sA, 1);
        sA += __shfl_xor_sync(0xffffffffu, sA, 2);
        sB += __shfl_xor_sync(0xffffffffu, sB, 1);
        sB += __shfl_xor_sync(0xffffffffu, sB, 2);
        sumA[mi] = sA; sumB[mi] = sB;
    }

    // ---- O = P V, 3 passes ----
    float oacc[2][4][4];
#pragma unroll
    for (int mi = 0; mi < 2; mi++)
#pragma unroll
        for (int nh = 0; nh < 4; nh++)
#pragma unroll
            for (int c = 0; c < 4; c++) oacc[mi][nh][c] = 0.f;

    uint32_t vbase[3] = {smb + VH_OFF, smb + VL_OFF, smb + VH_OFF};

#pragma unroll 1
    for (int p = 0; p < 3; p++) {
        uint32_t vb = vbase[p];
        bool lo = (p == 2);
#pragma unroll
        for (int kc = 0; kc < 7; kc++) {
            uint32_t amat[2][4];
#pragma unroll
            for (int mi = 0; mi < 2; mi++) {
                int nt0 = 2 * kc, nt1 = nt0 + 1;
                float v0 = acc[mi][nt0][0], v1 = acc[mi][nt0][1];
                float v2 = acc[mi][nt0][2], v3 = acc[mi][nt0][3];
                float w0 = 0.f, w1 = 0.f, w2 = 0.f, w3 = 0.f;
                if (nt1 < 13) {
                    w0 = acc[mi][nt1][0]; w1 = acc[mi][nt1][1];
                    w2 = acc[mi][nt1][2]; w3 = acc[mi][nt1][3];
                }
                if (lo) {
                    v0 = lopart(v0); v1 = lopart(v1); v2 = lopart(v2); v3 = lopart(v3);
                    w0 = lopart(w0); w1 = lopart(w1); w2 = lopart(w2); w3 = lopart(w3);
                }
                amat[mi][0] = packbf(v0, v1);
                amat[mi][1] = packbf(v2, v3);
                amat[mi][2] = packbf(w0, w1);
                amat[mi][3] = packbf(w2, w3);
            }
            uint32_t vrow = (uint32_t)(kc * 16 + ((lane >> 3) & 1) * 8 + l8);
#pragma unroll
            for (int nh = 0; nh < 4; nh++) {
                uint32_t bf[2];
                ldsm_x2t(bf, vb + vrow * PITCH + nh * 16);
                mma_bf16(oacc[0][nh], amat[0], bf);
                mma_bf16(oacc[1][nh], amat[1], bf);
            }
        }
    }

    // ---- epilogue: scale by 1/rowsum, split hi/lo, write planes ----
    uint32_t* ohp = (uint32_t*)g_oh;
    uint32_t* olp = (uint32_t*)g_ol;
#pragma unroll
    for (int mi = 0; mi < 2; mi++) {
        int rA = wid * 32 + mi * 16 + rq;
        int rB = rA + 8;
        float invA = 1.0f / sumA[mi];
        float invB = 1.0f / sumB[mi];
#pragma unroll
        for (int nh = 0; nh < 4; nh++) {
            int col = h * 32 + nh * 8 + cq;
            if (rA < 98) {
                uint32_t hi, lo;
                split2(oacc[mi][nh][0] * invA, oacc[mi][nh][1] * invA, hi, lo);
                size_t idx = (((size_t)b * NTOK + rA) * 128 + col) >> 1;
                ohp[idx] = hi; olp[idx] = lo;
            }
            if (rB < 98) {
                uint32_t hi, lo;
                split2(oacc[mi][nh][2] * invB, oacc[mi][nh][3] * invB, hi, lo);
                size_t idx = (((size_t)b * NTOK + rB) * 128 + col) >> 1;
                ohp[idx] = hi; olp[idx] = lo;
            }
        }
    }
}

// ===========================================================================
extern "C" void kernel_launch(void* const* d_in, const int* in_sizes, int n_in,
                              void* d_out, int out_size) {
    const float* x          = (const float*)d_in[0];
    const float* mask       = (const float*)d_in[1];
    const float* qkv_w      = (const float*)d_in[2];
    const float* qkv_b      = (const float*)d_in[3];
    const float* proj_w     = (const float*)d_in[4];
    const float* proj_b     = (const float*)d_in[5];
    const float* bias_table = (const float*)d_in[6];
    const int*   rel_index  = (const int*)d_in[7];
    float* out = (float*)d_out;

    void *qh, *ql, *oh, *ol;
    cudaGetSymbolAddress(&qh, g_qh);
    cudaGetSymbolAddress(&ql, g_ql);
    cudaGetSymbolAddress(&oh, g_oh);
    cudaGetSymbolAddress(&ol, g_ol);

    cudaFuncSetAttribute(gemm_hmma<0, 1>,
                         cudaFuncAttributeMaxDynamicSharedMemorySize, GEMM_SMEM);
    cudaFuncSetAttribute(gemm_hmma<1, 0>,
                         cudaFuncAttributeMaxDynamicSharedMemorySize, GEMM_SMEM);
    cudaFuncSetAttribute(attn_hmma_kernel,
                         cudaFuncAttributeMaxDynamicSharedMemorySize, ATTN_SMEM);

    // 1. bias+mask combine
    build_sbm_kernel<<<dim3((NN + 255) / 256, NWIN * HEADS), 256>>>(bias_table, rel_index, mask);
    // 2. QKV projection: fp32 in -> bf16 hi/lo planes out
    gemm_hmma<0, 1><<<dim3(MTOT / 64, 3), 256, GEMM_SMEM>>>(
        x, nullptr, nullptr, qkv_w, qkv_b,
        nullptr, (uint32_t*)qh, (uint32_t*)ql, 384);
    // 3. attention (HMMA, bf16 planes in/out)
    attn_hmma_kernel<<<dim3(BATCH, HEADS), 128, ATTN_SMEM>>>();
    // 4. output projection: bf16 planes in -> fp32 out
    gemm_hmma<1, 0><<<dim3(MTOT / 64, 1), 256, GEMM_SMEM>>>(
        nullptr, (const __nv_bfloat16*)oh, (const __nv_bfloat16*)ol, proj_w, proj_b,
        out, nullptr, nullptr, 128);
}

// round 5
// speedup vs baseline: 1.6429x; 1.6429x over previous
#include <cuda_runtime.h>
#include <cuda_bf16.h>
#include <stdint.h>
#include <math.h>

#define BATCH 2048
#define NTOK 98
#define DIM 128
#define HEADS 4
#define NWIN 256
#define NN (NTOK * NTOK)   // 9604
#define MTOT (BATCH * NTOK)  // 200704

// Scratch (device globals)
__device__ float g_qkv[(size_t)MTOT * 384];                 // [m][s*128+h*32+d]
__device__ float g_att[(size_t)MTOT * 128];                 // [m][h*32+d]
__device__ __nv_bfloat16 g_sbm[(size_t)NWIN * HEADS * NN];  // bias+mask bf16

// ===========================================================================
__device__ __forceinline__ uint32_t smem_u32(const void* p) {
    uint32_t a;
    asm("{ .reg .u64 t; cvta.to.shared.u64 t, %1; cvt.u32.u64 %0, t; }" : "=r"(a) : "l"(p));
    return a;
}
__device__ __forceinline__ void ldsm_x4(uint32_t* r, uint32_t addr) {
    asm volatile("ldmatrix.sync.aligned.m8n8.x4.shared.b16 {%0,%1,%2,%3}, [%4];"
                 : "=r"(r[0]), "=r"(r[1]), "=r"(r[2]), "=r"(r[3]) : "r"(addr));
}
__device__ __forceinline__ void ldsm_x2(uint32_t* r, uint32_t addr) {
    asm volatile("ldmatrix.sync.aligned.m8n8.x2.shared.b16 {%0,%1}, [%2];"
                 : "=r"(r[0]), "=r"(r[1]) : "r"(addr));
}
__device__ __forceinline__ void ldsm_x2t(uint32_t* r, uint32_t addr) {
    asm volatile("ldmatrix.sync.aligned.m8n8.x2.trans.shared.b16 {%0,%1}, [%2];"
                 : "=r"(r[0]), "=r"(r[1]) : "r"(addr));
}
__device__ __forceinline__ void mma_bf16(float* d, const uint32_t* a, const uint32_t* b) {
    asm volatile("mma.sync.aligned.m16n8k16.row.col.f32.bf16.bf16.f32 "
                 "{%0,%1,%2,%3}, {%4,%5,%6,%7}, {%8,%9}, {%0,%1,%2,%3};"
                 : "+f"(d[0]), "+f"(d[1]), "+f"(d[2]), "+f"(d[3])
                 : "r"(a[0]), "r"(a[1]), "r"(a[2]), "r"(a[3]), "r"(b[0]), "r"(b[1]));
}
__device__ __forceinline__ uint32_t packbf(float a, float b) {
    __nv_bfloat162 t = __float22bfloat162_rn(make_float2(a, b));
    return *(uint32_t*)&t;
}
__device__ __forceinline__ float lopart(float v) {
    return v - __bfloat162float(__float2bfloat16(v));
}
__device__ __forceinline__ void split4(float4 v, uint2& hi, uint2& lo) {
    __nv_bfloat16 hx = __float2bfloat16(v.x), hy = __float2bfloat16(v.y);
    __nv_bfloat16 hz = __float2bfloat16(v.z), hw = __float2bfloat16(v.w);
    __nv_bfloat162 h0 = __halves2bfloat162(hx, hy), h1 = __halves2bfloat162(hz, hw);
    hi.x = *(uint32_t*)&h0; hi.y = *(uint32_t*)&h1;
    lo.x = packbf(v.x - __bfloat162float(hx), v.y - __bfloat162float(hy));
    lo.y = packbf(v.z - __bfloat162float(hz), v.w - __bfloat162float(hw));
}
// swizzled smem address: 256B-pitch rows, XOR 16B-chunk by row&7
__device__ __forceinline__ uint32_t swz(uint32_t r, uint32_t cb) {
    return (r << 8) + (cb ^ ((r & 7) << 4));
}

// ===========================================================================
// bias+mask combine
// ===========================================================================
__global__ void build_sbm_kernel(const float* __restrict__ table,
                                 const int* __restrict__ rel,
                                 const float* __restrict__ mask) {
    int nm = blockIdx.x * 256 + threadIdx.x;
    int wh = blockIdx.y;
    if (nm < NN) {
        int w = wh >> 2, h = wh & 3;
        float v = table[rel[nm] * HEADS + h] + mask[(size_t)w * NN + nm];
        g_sbm[(size_t)wh * NN + nm] = __float2bfloat16(v);
    }
}

// ===========================================================================
// HMMA GEMM: C[M][N] = A[M][128] @ W[N][128]^T + bias  (bf16 hi/lo 3-pass)
// Block: 64 M-rows; loops NITER tiles of 128 N-cols. A staged+split once.
// 256 threads (8 warps, warp tile 32x32). fp32 in, fp32 out.
// ===========================================================================
#define GEMM_SMEM 98304
#define AH_OFF 0
#define AL_OFF 16384
#define WH_OFF 32768
#define WL_OFF 65536

template<int NITER>
__global__ __launch_bounds__(256, 2) void gemm_hmma(
    const float* __restrict__ Af, const float* __restrict__ W,
    const float* __restrict__ bias, float* __restrict__ Cf)
{
    extern __shared__ char sm[];
    const uint32_t smb = smem_u32(sm);
    const int tid = threadIdx.x;
    const int wid = tid >> 5, lane = tid & 31;
    const size_t m0 = (size_t)blockIdx.x * 64;
    const int N = NITER * 128;

    // ---- stage A (64 rows x 128 cols, fp32 -> hi/lo), once ----
#pragma unroll
    for (int i = 0; i < 8; i++) {
        int idx = tid + 256 * i;           // 2048 = 64 rows * 32 float4
        int r = idx >> 5;
        int c4 = (idx & 31) << 2;
        float4 v = *(const float4*)(Af + (m0 + r) * 128 + c4);
        uint2 hi, lo;
        split4(v, hi, lo);
        *(uint2*)(sm + AH_OFF + swz(r, c4 * 2)) = hi;
        *(uint2*)(sm + AL_OFF + swz(r, c4 * 2)) = lo;
    }

    const int wm = (wid & 1) * 32;
    const int wn = (wid >> 1) * 32;
    const int rq = lane >> 2, cq = (lane & 3) * 2;

#pragma unroll 1
    for (int it = 0; it < NITER; it++) {
        const int n0 = it * 128;
        // ---- stage W tile (128 rows x 128 cols, fp32 -> hi/lo) ----
#pragma unroll
        for (int i = 0; i < 16; i++) {
            int idx = tid + 256 * i;       // 4096
            int r = idx >> 5;
            int c4 = (idx & 31) << 2;
            float4 v = *(const float4*)(W + (size_t)(n0 + r) * 128 + c4);
            uint2 hi, lo;
            split4(v, hi, lo);
            *(uint2*)(sm + WH_OFF + swz(r, c4 * 2)) = hi;
            *(uint2*)(sm + WL_OFF + swz(r, c4 * 2)) = lo;
        }
        __syncthreads();

        float acc[2][4][4];
#pragma unroll
        for (int mi = 0; mi < 2; mi++)
#pragma unroll
            for (int ni = 0; ni < 4; ni++)
#pragma unroll
                for (int c = 0; c < 4; c++) acc[mi][ni][c] = 0.f;

#pragma unroll
        for (int kc = 0; kc < 8; kc++) {
            uint32_t cb = (uint32_t)(kc * 32 + ((lane >> 4) & 1) * 16);
            uint32_t ah[2][4], al[2][4], bh[2][4], bl[2][4];
#pragma unroll
            for (int mi = 0; mi < 2; mi++) {
                uint32_t r = (uint32_t)(wm + mi * 16 + (lane & 15));
                ldsm_x4(ah[mi], smb + AH_OFF + swz(r, cb));
                ldsm_x4(al[mi], smb + AL_OFF + swz(r, cb));
            }
#pragma unroll
            for (int g = 0; g < 2; g++) {
                uint32_t r = (uint32_t)(wn + g * 16 + (lane & 15));
                ldsm_x4(bh[g], smb + WH_OFF + swz(r, cb));
                ldsm_x4(bl[g], smb + WL_OFF + swz(r, cb));
            }
#pragma unroll
            for (int mi = 0; mi < 2; mi++)
#pragma unroll
                for (int ni = 0; ni < 4; ni++) {
                    int g = ni >> 1, hf = ni & 1;
                    uint32_t B0[2]  = {bh[g][hf], bh[g][hf + 2]};
                    uint32_t Bl0[2] = {bl[g][hf], bl[g][hf + 2]};
                    mma_bf16(acc[mi][ni], ah[mi], B0);
                    mma_bf16(acc[mi][ni], al[mi], B0);
                    mma_bf16(acc[mi][ni], ah[mi], Bl0);
                }
        }

        // ---- epilogue (fp32) ----
#pragma unroll
        for (int mi = 0; mi < 2; mi++) {
            size_t rA = m0 + wm + mi * 16 + rq;
            size_t rB = rA + 8;
#pragma unroll
            for (int ni = 0; ni < 4; ni++) {
                int col = n0 + wn + ni * 8 + cq;
                float b0 = bias[col], b1 = bias[col + 1];
                *(float2*)(Cf + rA * N + col) =
                    make_float2(acc[mi][ni][0] + b0, acc[mi][ni][1] + b1);
                *(float2*)(Cf + rB * N + col) =
                    make_float2(acc[mi][ni][2] + b0, acc[mi][ni][3] + b1);
            }
        }
        __syncthreads();   // W tile free for next iteration
    }
}

// ===========================================================================
// HMMA attention (R3 version): one CTA per (window, head), 128 threads.
// ===========================================================================
#define PITCH 80
#define QH_OFF 0
#define QL_OFF 10240
#define KH_OFF 20480
#define KL_OFF 29440
#define VH_OFF 38400
#define VL_OFF 47360
#define SB_OFF 56320
#define ATTN_SMEM 75584

__global__ __launch_bounds__(128) void attn_hmma_kernel() {
    extern __shared__ char smraw[];
    const uint32_t smb = smem_u32(smraw);
    char* sm = smraw;

    const int b = blockIdx.x, h = blockIdx.y;
    const int tid = threadIdx.x;
    const int wid = tid >> 5, lane = tid & 31;

    // zero operand tiles (pads must be exactly 0)
    {
        float4 z = make_float4(0.f, 0.f, 0.f, 0.f);
        float4* p = (float4*)sm;
#pragma unroll
        for (int i = 0; i < 28; i++) {
            int idx = tid + 128 * i;
            if (idx < 3520) p[idx] = z;
        }
    }
    __syncthreads();

    // load Q (scaled) / K / V, split hi/lo bf16, pitch-80 rows
    const float scale = 0.17677669529663687f;
    const float* qg = g_qkv + ((size_t)b * NTOK) * 384 + h * 32;
    for (int idx = tid; idx < NTOK * 8; idx += 128) {
        int n = idx >> 3, c4 = (idx & 7) << 2;
        const float* src = qg + (size_t)n * 384 + c4;
        uint32_t off = (uint32_t)(n * PITCH + c4 * 2);
        uint2 hi, lo;

        float4 q = *(const float4*)src;
        q.x *= scale; q.y *= scale; q.z *= scale; q.w *= scale;
        split4(q, hi, lo);
        *(uint2*)(sm + QH_OFF + off) = hi;
        *(uint2*)(sm + QL_OFF + off) = lo;

        split4(*(const float4*)(src + 128), hi, lo);
        *(uint2*)(sm + KH_OFF + off) = hi;
        *(uint2*)(sm + KL_OFF + off) = lo;

        split4(*(const float4*)(src + 256), hi, lo);
        *(uint2*)(sm + VH_OFF + off) = hi;
        *(uint2*)(sm + VL_OFF + off) = lo;
    }
    // stage bias+mask tile
    {
        const uint32_t* src = (const uint32_t*)(g_sbm + ((size_t)((b & (NWIN - 1)) * HEADS + h)) * NN);
        uint32_t* dst = (uint32_t*)(sm + SB_OFF);
        for (int i = tid; i < NN / 2; i += 128) dst[i] = src[i];
    }
    __syncthreads();

    const int l8 = lane & 7;
    const int rq = lane >> 2;
    const int cq = (lane & 3) * 2;

    // ---- S = QK^T, 3 passes ----
    float acc[2][13][4];
#pragma unroll
    for (int mi = 0; mi < 2; mi++)
#pragma unroll
        for (int nt = 0; nt < 13; nt++)
#pragma unroll
            for (int c = 0; c < 4; c++) acc[mi][nt][c] = 0.f;

    uint32_t qbase[3] = {smb + QH_OFF, smb + QH_OFF, smb + QL_OFF};
    uint32_t kbase[3] = {smb + KH_OFF, smb + KL_OFF, smb + KH_OFF};

#pragma unroll 1
    for (int p = 0; p < 3; p++) {
        uint32_t qb = qbase[p], kb = kbase[p];
#pragma unroll
        for (int kc = 0; kc < 2; kc++) {
            int sel = lane >> 3;
            uint32_t arow = (uint32_t)(wid * 32 + (sel & 1) * 8 + l8);
            uint32_t aoff = (uint32_t)(kc * 32 + (sel >> 1) * 16);
            uint32_t a0[4], a1[4];
            ldsm_x4(a0, qb + arow * PITCH + aoff);
            ldsm_x4(a1, qb + (arow + 16) * PITCH + aoff);
            uint32_t boff = (uint32_t)(kc * 32 + ((lane >> 3) & 1) * 16);
#pragma unroll
            for (int nt = 0; nt < 13; nt++) {
                uint32_t bf[2];
                ldsm_x2(bf, kb + (uint32_t)(nt * 8 + l8) * PITCH + boff);
                mma_bf16(acc[0][nt], a0, bf);
                mma_bf16(acc[1][nt], a1, bf);
            }
        }
    }

    // ---- bias+mask add, softmax ----
    float sumA[2], sumB[2];
#pragma unroll
    for (int mi = 0; mi < 2; mi++) {
        int rA = wid * 32 + mi * 16 + rq;
        int rB = rA + 8;
        float mxA = -1e30f, mxB = -1e30f;
#pragma unroll
        for (int nt = 0; nt < 13; nt++) {
            int col = nt * 8 + cq;
            if (col < 98) {
                if (rA < 98) {
                    uint32_t u = *(const uint32_t*)(sm + SB_OFF + rA * 196 + col * 2);
                    __nv_bfloat162 bb = *(__nv_bfloat162*)&u;
                    acc[mi][nt][0] += __bfloat162float(bb.x);
                    acc[mi][nt][1] += __bfloat162float(bb.y);
                }
                if (rB < 98) {
                    uint32_t u = *(const uint32_t*)(sm + SB_OFF + rB * 196 + col * 2);
                    __nv_bfloat162 bb = *(__nv_bfloat162*)&u;
                    acc[mi][nt][2] += __bfloat162float(bb.x);
                    acc[mi][nt][3] += __bfloat162float(bb.y);
                }
            } else {
                acc[mi][nt][0] = -1e30f; acc[mi][nt][1] = -1e30f;
                acc[mi][nt][2] = -1e30f; acc[mi][nt][3] = -1e30f;
            }
            mxA = fmaxf(mxA, fmaxf(acc[mi][nt][0], acc[mi][nt][1]));
            mxB = fmaxf(mxB, fmaxf(acc[mi][nt][2], acc[mi][nt][3]));
        }
        mxA = fmaxf(mxA, __shfl_xor_sync(0xffffffffu, mxA, 1));
        mxA = fmaxf(mxA, __shfl_xor_sync(0xffffffffu, mxA, 2));
        mxB = fmaxf(mxB, __shfl_xor_sync(0xffffffffu, mxB, 1));
        mxB = fmaxf(mxB, __shfl_xor_sync(0xffffffffu, mxB, 2));
        float sA = 0.f, sB = 0.f;
#pragma unroll
        for (int nt = 0; nt < 13; nt++) {
            float e0 = __expf(acc[mi][nt][0] - mxA);
            float e1 = __expf(acc[mi][nt][1] - mxA);
            float e2 = __expf(acc[mi][nt][2] - mxB);
            float e3 = __expf(acc[mi][nt][3] - mxB);
            acc[mi][nt][0] = e0; acc[mi][nt][1] = e1;
            acc[mi][nt][2] = e2; acc[mi][nt][3] = e3;
            sA += e0 + e1; sB += e2 + e3;
        }
        sA += __shfl_xor_sync(0xffffffffu, sA, 1);
        sA += __shfl_xor_sync(0xffffffffu, sA, 2);
        sB += __shfl_xor_sync(0xffffffffu, sB, 1);
        sB += __shfl_xor_sync(0xffffffffu, sB, 2);
        sumA[mi] = sA; sumB[mi] = sB;
    }

    // ---- O = P V, 3 passes ----
    float oacc[2][4][4];
#pragma unroll
    for (int mi = 0; mi < 2; mi++)
#pragma unroll
        for (int nh = 0; nh < 4; nh++)
#pragma unroll
            for (int c = 0; c < 4; c++) oacc[mi][nh][c] = 0.f;

    uint32_t vbase[3] = {smb + VH_OFF, smb + VL_OFF, smb + VH_OFF};

#pragma unroll 1
    for (int p = 0; p < 3; p++) {
        uint32_t vb = vbase[p];
        bool lo = (p == 2);
#pragma unroll
        for (int kc = 0; kc < 7; kc++) {
            uint32_t amat[2][4];
#pragma unroll
            for (int mi = 0; mi < 2; mi++) {
                int nt0 = 2 * kc, nt1 = nt0 + 1;
                float v0 = acc[mi][nt0][0], v1 = acc[mi][nt0][1];
                float v2 = acc[mi][nt0][2], v3 = acc[mi][nt0][3];
                float w0 = 0.f, w1 = 0.f, w2 = 0.f, w3 = 0.f;
                if (nt1 < 13) {
                    w0 = acc[mi][nt1][0]; w1 = acc[mi][nt1][1];
                    w2 = acc[mi][nt1][2]; w3 = acc[mi][nt1][3];
                }
                if (lo) {
                    v0 = lopart(v0); v1 = lopart(v1); v2 = lopart(v2); v3 = lopart(v3);
                    w0 = lopart(w0); w1 = lopart(w1); w2 = lopart(w2); w3 = lopart(w3);
                }
                amat[mi][0] = packbf(v0, v1);
                amat[mi][1] = packbf(v2, v3);
                amat[mi][2] = packbf(w0, w1);
                amat[mi][3] = packbf(w2, w3);
            }
            uint32_t vrow = (uint32_t)(kc * 16 + ((lane >> 3) & 1) * 8 + l8);
#pragma unroll
            for (int nh = 0; nh < 4; nh++) {
                uint32_t bf[2];
                ldsm_x2t(bf, vb + vrow * PITCH + nh * 16);
                mma_bf16(oacc[0][nh], amat[0], bf);
                mma_bf16(oacc[1][nh], amat[1], bf);
            }
        }
    }

    // ---- epilogue ----
#pragma unroll
    for (int mi = 0; mi < 2; mi++) {
        int rA = wid * 32 + mi * 16 + rq;
        int rB = rA + 8;
        float invA = 1.0f / sumA[mi];
        float invB = 1.0f / sumB[mi];
#pragma unroll
        for (int nh = 0; nh < 4; nh++) {
            int col = nh * 8 + cq;
            if (rA < 98) {
                float2 o = make_float2(oacc[mi][nh][0] * invA, oacc[mi][nh][1] * invA);
                *(float2*)(g_att + ((size_t)b * NTOK + rA) * 128 + h * 32 + col) = o;
            }
            if (rB < 98) {
                float2 o = make_float2(oacc[mi][nh][2] * invB, oacc[mi][nh][3] * invB);
                *(float2*)(g_att + ((size_t)b * NTOK + rB) * 128 + h * 32 + col) = o;
            }
        }
    }
}

// ===========================================================================
extern "C" void kernel_launch(void* const* d_in, const int* in_sizes, int n_in,
                              void* d_out, int out_size) {
    const float* x          = (const float*)d_in[0];
    const float* mask       = (const float*)d_in[1];
    const float* qkv_w      = (const float*)d_in[2];
    const float* qkv_b      = (const float*)d_in[3];
    const float* proj_w     = (const float*)d_in[4];
    const float* proj_b     = (const float*)d_in[5];
    const float* bias_table = (const float*)d_in[6];
    const int*   rel_index  = (const int*)d_in[7];
    float* out = (float*)d_out;

    void *qkv_ptr, *att_ptr;
    cudaGetSymbolAddress(&qkv_ptr, g_qkv);
    cudaGetSymbolAddress(&att_ptr, g_att);

    cudaFuncSetAttribute(gemm_hmma<3>,
                         cudaFuncAttributeMaxDynamicSharedMemorySize, GEMM_SMEM);
    cudaFuncSetAttribute(gemm_hmma<1>,
                         cudaFuncAttributeMaxDynamicSharedMemorySize, GEMM_SMEM);
    cudaFuncSetAttribute(attn_hmma_kernel,
                         cudaFuncAttributeMaxDynamicSharedMemorySize, ATTN_SMEM);

    // 1. bias+mask combine
    build_sbm_kernel<<<dim3((NN + 255) / 256, NWIN * HEADS), 256>>>(bias_table, rel_index, mask);
    // 2. QKV projection: A staged once, 3 W tiles looped
    gemm_hmma<3><<<MTOT / 64, 256, GEMM_SMEM>>>(x, qkv_w, qkv_b, (float*)qkv_ptr);
    // 3. attention (HMMA)
    attn_hmma_kernel<<<dim3(BATCH, HEADS), 128, ATTN_SMEM>>>();
    // 4. output projection
    gemm_hmma<1><<<MTOT / 64, 256, GEMM_SMEM>>>((const float*)att_ptr, proj_w, proj_b, out);
}

// round 7
// speedup vs baseline: 1.6591x; 1.0098x over previous
#include <cuda_runtime.h>
#include <cuda_bf16.h>
#include <stdint.h>
#include <math.h>

#define BATCH 2048
#define NTOK 98
#define DIM 128
#define HEADS 4
#define NWIN 256
#define NN (NTOK * NTOK)   // 9604
#define MTOT (BATCH * NTOK)  // 200704

// Scratch (device globals)
__device__ float g_qkv[(size_t)MTOT * 384];                 // [m][s*128+h*32+d]
__device__ float g_att[(size_t)MTOT * 128];                 // [m][h*32+d]
__device__ __nv_bfloat16 g_sbm[(size_t)NWIN * HEADS * NN];  // bias+mask bf16
__device__ char g_wh[4 * 32768];                            // W hi, smem-image layout
__device__ char g_wl[4 * 32768];                            // W lo

// ===========================================================================
__device__ __forceinline__ uint32_t smem_u32(const void* p) {
    uint32_t a;
    asm("{ .reg .u64 t; cvta.to.shared.u64 t, %1; cvt.u32.u64 %0, t; }" : "=r"(a) : "l"(p));
    return a;
}
__device__ __forceinline__ void ldsm_x4(uint32_t* r, uint32_t addr) {
    asm volatile("ldmatrix.sync.aligned.m8n8.x4.shared.b16 {%0,%1,%2,%3}, [%4];"
                 : "=r"(r[0]), "=r"(r[1]), "=r"(r[2]), "=r"(r[3]) : "r"(addr));
}
__device__ __forceinline__ void ldsm_x2(uint32_t* r, uint32_t addr) {
    asm volatile("ldmatrix.sync.aligned.m8n8.x2.shared.b16 {%0,%1}, [%2];"
                 : "=r"(r[0]), "=r"(r[1]) : "r"(addr));
}
__device__ __forceinline__ void ldsm_x2t(uint32_t* r, uint32_t addr) {
    asm volatile("ldmatrix.sync.aligned.m8n8.x2.trans.shared.b16 {%0,%1}, [%2];"
                 : "=r"(r[0]), "=r"(r[1]) : "r"(addr));
}
__device__ __forceinline__ void mma_bf16(float* d, const uint32_t* a, const uint32_t* b) {
    asm volatile("mma.sync.aligned.m16n8k16.row.col.f32.bf16.bf16.f32 "
                 "{%0,%1,%2,%3}, {%4,%5,%6,%7}, {%8,%9}, {%0,%1,%2,%3};"
                 : "+f"(d[0]), "+f"(d[1]), "+f"(d[2]), "+f"(d[3])
                 : "r"(a[0]), "r"(a[1]), "r"(a[2]), "r"(a[3]), "r"(b[0]), "r"(b[1]));
}
__device__ __forceinline__ uint32_t packbf(float a, float b) {
    __nv_bfloat162 t = __float22bfloat162_rn(make_float2(a, b));
    return *(uint32_t*)&t;
}
__device__ __forceinline__ float lopart(float v) {
    return v - __bfloat162float(__float2bfloat16(v));
}
__device__ __forceinline__ void split4(float4 v, uint2& hi, uint2& lo) {
    __nv_bfloat16 hx = __float2bfloat16(v.x), hy = __float2bfloat16(v.y);
    __nv_bfloat16 hz = __float2bfloat16(v.z), hw = __float2bfloat16(v.w);
    __nv_bfloat162 h0 = __halves2bfloat162(hx, hy), h1 = __halves2bfloat162(hz, hw);
    hi.x = *(uint32_t*)&h0; hi.y = *(uint32_t*)&h1;
    lo.x = packbf(v.x - __bfloat162float(hx), v.y - __bfloat162float(hy));
    lo.y = packbf(v.z - __bfloat162float(hz), v.w - __bfloat162float(hw));
}
// swizzled smem address: 256B-pitch rows, XOR 16B-chunk by row&7
__device__ __forceinline__ uint32_t swz(uint32_t r, uint32_t cb) {
    return (r << 8) + (cb ^ ((r & 7) << 4));
}

// ===========================================================================
// bias+mask combine
// ===========================================================================
__global__ void build_sbm_kernel(const float* __restrict__ table,
                                 const int* __restrict__ rel,
                                 const float* __restrict__ mask) {
    int nm = blockIdx.x * 256 + threadIdx.x;
    int wh = blockIdx.y;
    if (nm < NN) {
        int w = wh >> 2, h = wh & 3;
        float v = table[rel[nm] * HEADS + h] + mask[(size_t)w * NN + nm];
        g_sbm[(size_t)wh * NN + nm] = __float2bfloat16(v);
    }
}

// ===========================================================================
// W pre-split: fp32 W -> hi/lo bf16 in final swizzled smem-image layout.
// Tiles: 0..2 = qkv_w rows [t*128,(t+1)*128), 3 = proj_w.
// ===========================================================================
__global__ void split_w_kernel(const float* __restrict__ qkv_w,
                               const float* __restrict__ proj_w) {
    int idx = blockIdx.x * 256 + threadIdx.x;   // 16384 total
    int tile = idx >> 12;
    int r = (idx >> 5) & 127;
    int c4 = (idx & 31) << 2;
    const float* W = (tile < 3) ? qkv_w + (size_t)(tile * 128 + r) * 128 + c4
                                : proj_w + (size_t)r * 128 + c4;
    float4 v = *(const float4*)W;
    uint2 hi, lo;
    split4(v, hi, lo);
    uint32_t off = (uint32_t)(tile * 32768) + swz((uint32_t)r, (uint32_t)(c4 * 2));
    *(uint2*)(g_wh + off) = hi;
    *(uint2*)(g_wl + off) = lo;
}

// ===========================================================================
// HMMA GEMM: C[M][N] = A[M][128] @ W[N][128]^T + bias  (bf16 hi/lo 3-pass)
// Block: 64 M-rows; loops NITER tiles of 128 N-cols. A staged+split once.
// W tiles copied from pre-split image (no ALU). 256 threads, 8 warps 32x32.
// ===========================================================================
#define GEMM_SMEM 98304
#define AH_OFF 0
#define AL_OFF 16384
#define WH_OFF 32768
#define WL_OFF 65536

template<int NITER>
__global__ __launch_bounds__(256, 2) void gemm_hmma(
    const float* __restrict__ Af, const char* __restrict__ Whimg,
    const char* __restrict__ Wlimg, const float* __restrict__ bias,
    float* __restrict__ Cf)
{
    extern __shared__ char sm[];
    const uint32_t smb = smem_u32(sm);
    const int tid = threadIdx.x;
    const int wid = tid >> 5, lane = tid & 31;
    const size_t m0 = (size_t)blockIdx.x * 64;
    const int N = NITER * 128;

    // ---- stage A (64 rows x 128 cols, fp32 -> hi/lo), once ----
#pragma unroll
    for (int i = 0; i < 8; i++) {
        int idx = tid + 256 * i;
        int r = idx >> 5;
        int c4 = (idx & 31) << 2;
        float4 v = *(const float4*)(Af + (m0 + r) * 128 + c4);
        uint2 hi, lo;
        split4(v, hi, lo);
        *(uint2*)(sm + AH_OFF + swz(r, c4 * 2)) = hi;
        *(uint2*)(sm + AL_OFF + swz(r, c4 * 2)) = lo;
    }

    const int wm = (wid & 1) * 32;
    const int wn = (wid >> 1) * 32;
    const int rq = lane >> 2, cq = (lane & 3) * 2;

#pragma unroll 1
    for (int it = 0; it < NITER; it++) {
        const int n0 = it * 128;
        // ---- copy pre-split W tile image (pure uint4 copies) ----
        {
            const uint4* wh = (const uint4*)(Whimg + it * 32768);
            const uint4* wl = (const uint4*)(Wlimg + it * 32768);
#pragma unroll
            for (int i = 0; i < 8; i++) {
                int idx = tid + 256 * i;    // 2048
                *(uint4*)(sm + WH_OFF + idx * 16) = wh[idx];
                *(uint4*)(sm + WL_OFF + idx * 16) = wl[idx];
            }
        }
        __syncthreads();

        float acc[2][4][4];
#pragma unroll
        for (int mi = 0; mi < 2; mi++)
#pragma unroll
            for (int ni = 0; ni < 4; ni++)
#pragma unroll
                for (int c = 0; c < 4; c++) acc[mi][ni][c] = 0.f;

#pragma unroll
        for (int kc = 0; kc < 8; kc++) {
            uint32_t cb = (uint32_t)(kc * 32 + ((lane >> 4) & 1) * 16);
            uint32_t ah[2][4], al[2][4], bh[2][4], bl[2][4];
#pragma unroll
            for (int mi = 0; mi < 2; mi++) {
                uint32_t r = (uint32_t)(wm + mi * 16 + (lane & 15));
                ldsm_x4(ah[mi], smb + AH_OFF + swz(r, cb));
                ldsm_x4(al[mi], smb + AL_OFF + swz(r, cb));
            }
#pragma unroll
            for (int g = 0; g < 2; g++) {
                uint32_t r = (uint32_t)(wn + g * 16 + (lane & 15));
                ldsm_x4(bh[g], smb + WH_OFF + swz(r, cb));
                ldsm_x4(bl[g], smb + WL_OFF + swz(r, cb));
            }
#pragma unroll
            for (int mi = 0; mi < 2; mi++)
#pragma unroll
                for (int ni = 0; ni < 4; ni++) {
                    int g = ni >> 1, hf = ni & 1;
                    uint32_t B0[2]  = {bh[g][hf], bh[g][hf + 2]};
                    uint32_t Bl0[2] = {bl[g][hf], bl[g][hf + 2]};
                    mma_bf16(acc[mi][ni], ah[mi], B0);
                    mma_bf16(acc[mi][ni], al[mi], B0);
                    mma_bf16(acc[mi][ni], ah[mi], Bl0);
                }
        }

        // ---- epilogue (fp32) ----
#pragma unroll
        for (int mi = 0; mi < 2; mi++) {
            size_t rA = m0 + wm + mi * 16 + rq;
            size_t rB = rA + 8;
#pragma unroll
            for (int ni = 0; ni < 4; ni++) {
                int col = n0 + wn + ni * 8 + cq;
                float b0 = bias[col], b1 = bias[col + 1];
                *(float2*)(Cf + rA * N + col) =
                    make_float2(acc[mi][ni][0] + b0, acc[mi][ni][1] + b1);
                *(float2*)(Cf + rB * N + col) =
                    make_float2(acc[mi][ni][2] + b0, acc[mi][ni][3] + b1);
            }
        }
        __syncthreads();
    }
}

// ===========================================================================
// HMMA attention: one CTA per (window, head), 256 threads (8 warps x 16 rows).
// No SB smem staging (bias read from L2). Warp 7 (all-pad rows) exits early.
// ===========================================================================
#define PITCH 80
#define QH_OFF 0
#define QL_OFF 10240
#define KH_OFF 20480
#define KL_OFF 29440
#define VH_OFF 38400
#define VL_OFF 47360
#define ATTN_SMEM 56320

__global__ __launch_bounds__(256) void attn_hmma_kernel() {
    extern __shared__ char smraw[];
    const uint32_t smb = smem_u32(smraw);
    char* sm = smraw;

    const int b = blockIdx.x, h = blockIdx.y;
    const int tid = threadIdx.x;
    const int wid = tid >> 5, lane = tid & 31;

    // ---- zero only pad rows (98..111) of all 6 tiles ----
    {
        uint4 z = make_uint4(0, 0, 0, 0);
        // 6 tiles x 14 rows x 5 chunks = 420
        for (int idx = tid; idx < 420; idx += 256) {
            int t = idx / 70;            // tile 0..5
            int rem = idx - t * 70;
            int row = 98 + rem / 5;
            int ch = rem % 5;
            uint32_t base = (t < 2) ? (uint32_t)(t * 10240)
                                    : (uint32_t)(20480 + (t - 2) * 8960);
            *(uint4*)(sm + base + row * PITCH + ch * 16) = z;
        }
    }
    __syncthreads();

    // ---- load Q (scaled) / K / V, split hi/lo bf16, pitch-80 rows ----
    const float scale = 0.17677669529663687f;
    const float* qg = g_qkv + ((size_t)b * NTOK) * 384 + h * 32;
    for (int idx = tid; idx < NTOK * 8; idx += 256) {
        int n = idx >> 3, c4 = (idx & 7) << 2;
        const float* src = qg + (size_t)n * 384 + c4;
        uint32_t off = (uint32_t)(n * PITCH + c4 * 2);
        uint2 hi, lo;

        float4 q = *(const float4*)src;
        q.x *= scale; q.y *= scale; q.z *= scale; q.w *= scale;
        split4(q, hi, lo);
        *(uint2*)(sm + QH_OFF + off) = hi;
        *(uint2*)(sm + QL_OFF + off) = lo;

        split4(*(const float4*)(src + 128), hi, lo);
        *(uint2*)(sm + KH_OFF + off) = hi;
        *(uint2*)(sm + KL_OFF + off) = lo;

        split4(*(const float4*)(src + 256), hi, lo);
        *(uint2*)(sm + VH_OFF + off) = hi;
        *(uint2*)(sm + VL_OFF + off) = lo;
    }
    __syncthreads();

    if (wid == 7) return;   // rows 112..127 are pure padding

    const int l8 = lane & 7;
    const int rq = lane >> 2;
    const int cq = (lane & 3) * 2;

    // ---- S = QK^T, 3 passes; warp owns rows [16*wid, 16*wid+16) ----
    float acc[13][4];
#pragma unroll
    for (int nt = 0; nt < 13; nt++)
#pragma unroll
        for (int c = 0; c < 4; c++) acc[nt][c] = 0.f;

    uint32_t qbase[3] = {smb + QH_OFF, smb + QH_OFF, smb + QL_OFF};
    uint32_t kbase[3] = {smb + KH_OFF, smb + KL_OFF, smb + KH_OFF};

#pragma unroll 1
    for (int p = 0; p < 3; p++) {
        uint32_t qb = qbase[p], kb = kbase[p];
#pragma unroll
        for (int kc = 0; kc < 2; kc++) {
            uint32_t r = (uint32_t)(wid * 16 + (lane & 15));
            uint32_t aoff = (uint32_t)(kc * 32 + ((lane >> 4) & 1) * 16);
            uint32_t a[4];
            ldsm_x4(a, qb + r * PITCH + aoff);
            uint32_t boff = (uint32_t)(kc * 32 + ((lane >> 3) & 1) * 16);
#pragma unroll
            for (int nt = 0; nt < 13; nt++) {
                uint32_t bf[2];
                ldsm_x2(bf, kb + (uint32_t)(nt * 8 + l8) * PITCH + boff);
                mma_bf16(acc[nt], a, bf);
            }
        }
    }

    // ---- bias+mask add (direct from gmem), softmax ----
    const __nv_bfloat16* sbm = g_sbm + ((size_t)((b & (NWIN - 1)) * HEADS + h)) * NN;
    const int rA = wid * 16 + rq;
    const int rB = rA + 8;
    float mxA = -1e30f, mxB = -1e30f;
#pragma unroll
    for (int nt = 0; nt < 13; nt++) {
        int col = nt * 8 + cq;
        if (col < 98) {
            if (rA < 98) {
                uint32_t u = __ldg((const uint32_t*)(sbm + rA * 98 + col));
                __nv_bfloat162 bb = *(__nv_bfloat162*)&u;
                acc[nt][0] += __bfloat162float(bb.x);
                acc[nt][1] += __bfloat162float(bb.y);
            }
            if (rB < 98) {
                uint32_t u = __ldg((const uint32_t*)(sbm + rB * 98 + col));
                __nv_bfloat162 bb = *(__nv_bfloat162*)&u;
                acc[nt][2] += __bfloat162float(bb.x);
                acc[nt][3] += __bfloat162float(bb.y);
            }
        } else {
            acc[nt][0] = -1e30f; acc[nt][1] = -1e30f;
            acc[nt][2] = -1e30f; acc[nt][3] = -1e30f;
        }
        mxA = fmaxf(mxA, fmaxf(acc[nt][0], acc[nt][1]));
        mxB = fmaxf(mxB, fmaxf(acc[nt][2], acc[nt][3]));
    }
    mxA = fmaxf(mxA, __shfl_xor_sync(0xffffffffu, mxA, 1));
    mxA = fmaxf(mxA, __shfl_xor_sync(0xffffffffu, mxA, 2));
    mxB = fmaxf(mxB, __shfl_xor_sync(0xffffffffu, mxB, 1));
    mxB = fmaxf(mxB, __shfl_xor_sync(0xffffffffu, mxB, 2));
    float sA = 0.f, sB = 0.f;
#pragma unroll
    for (int nt = 0; nt < 13; nt++) {
        float e0 = __expf(acc[nt][0] - mxA);
        float e1 = __expf(acc[nt][1] - mxA);
        float e2 = __expf(acc[nt][2] - mxB);
        float e3 = __expf(acc[nt][3] - mxB);
        acc[nt][0] = e0; acc[nt][1] = e1;
        acc[nt][2] = e2; acc[nt][3] = e3;
        sA += e0 + e1; sB += e2 + e3;
    }
    sA += __shfl_xor_sync(0xffffffffu, sA, 1);
    sA += __shfl_xor_sync(0xffffffffu, sA, 2);
    sB += __shfl_xor_sync(0xffffffffu, sB, 1);
    sB += __shfl_xor_sync(0xffffffffu, sB, 2);

    // ---- O = P V, 3 passes ----
    float oacc[4][4];
#pragma unroll
    for (int nh = 0; nh < 4; nh++)
#pragma unroll
        for (int c = 0; c < 4; c++) oacc[nh][c] = 0.f;

    uint32_t vbase[3] = {smb + VH_OFF, smb + VL_OFF, smb + VH_OFF};

#pragma unroll 1
    for (int p = 0; p < 3; p++) {
        uint32_t vb = vbase[p];
        bool lo = (p == 2);
#pragma unroll
        for (int kc = 0; kc < 7; kc++) {
            int nt0 = 2 * kc, nt1 = nt0 + 1;
            float v0 = acc[nt0][0], v1 = acc[nt0][1];
            float v2 = acc[nt0][2], v3 = acc[nt0][3];
            float w0 = 0.f, w1 = 0.f, w2 = 0.f, w3 = 0.f;
            if (nt1 < 13) {
                w0 = acc[nt1][0]; w1 = acc[nt1][1];
                w2 = acc[nt1][2]; w3 = acc[nt1][3];
            }
            if (lo) {
                v0 = lopart(v0); v1 = lopart(v1); v2 = lopart(v2); v3 = lopart(v3);
                w0 = lopart(w0); w1 = lopart(w1); w2 = lopart(w2); w3 = lopart(w3);
            }
            uint32_t amat[4];
            amat[0] = packbf(v0, v1);
            amat[1] = packbf(v2, v3);
            amat[2] = packbf(w0, w1);
            amat[3] = packbf(w2, w3);
            uint32_t vrow = (uint32_t)(kc * 16 + ((lane >> 3) & 1) * 8 + l8);
#pragma unroll
            for (int nh = 0; nh < 4; nh++) {
                uint32_t bf[2];
                ldsm_x2t(bf, vb + vrow * PITCH + nh * 16);
                mma_bf16(oacc[nh], amat, bf);
            }
        }
    }

    // ---- epilogue ----
    float invA = 1.0f / sA;
    float invB = 1.0f / sB;
#pragma unroll
    for (int nh = 0; nh < 4; nh++) {
        int col = nh * 8 + cq;
        if (rA < 98) {
            float2 o = make_float2(oacc[nh][0] * invA, oacc[nh][1] * invA);
            *(float2*)(g_att + ((size_t)b * NTOK + rA) * 128 + h * 32 + col) = o;
        }
        if (rB < 98) {
            float2 o = make_float2(oacc[nh][2] * invB, oacc[nh][3] * invB);
            *(float2*)(g_att + ((size_t)b * NTOK + rB) * 128 + h * 32 + col) = o;
        }
    }
}

// ===========================================================================
extern "C" void kernel_launch(void* const* d_in, const int* in_sizes, int n_in,
                              void* d_out, int out_size) {
    const float* x          = (const float*)d_in[0];
    const float* mask       = (const float*)d_in[1];
    const float* qkv_w      = (const float*)d_in[2];
    const float* qkv_b      = (const float*)d_in[3];
    const float* proj_w     = (const float*)d_in[4];
    const float* proj_b     = (const float*)d_in[5];
    const float* bias_table = (const float*)d_in[6];
    const int*   rel_index  = (const int*)d_in[7];
    float* out = (float*)d_out;

    void *qkv_ptr, *att_ptr, *whp, *wlp;
    cudaGetSymbolAddress(&qkv_ptr, g_qkv);
    cudaGetSymbolAddress(&att_ptr, g_att);
    cudaGetSymbolAddress(&whp, g_wh);
    cudaGetSymbolAddress(&wlp, g_wl);

    cudaFuncSetAttribute(gemm_hmma<3>,
                         cudaFuncAttributeMaxDynamicSharedMemorySize, GEMM_SMEM);
    cudaFuncSetAttribute(gemm_hmma<1>,
                         cudaFuncAttributeMaxDynamicSharedMemorySize, GEMM_SMEM);
    cudaFuncSetAttribute(attn_hmma_kernel,
                         cudaFuncAttributeMaxDynamicSharedMemorySize, ATTN_SMEM);

    // 1. bias+mask combine + W pre-split (independent prep)
    build_sbm_kernel<<<dim3((NN + 255) / 256, NWIN * HEADS), 256>>>(bias_table, rel_index, mask);
    split_w_kernel<<<64, 256>>>(qkv_w, proj_w);
    // 2. QKV projection
    gemm_hmma<3><<<MTOT / 64, 256, GEMM_SMEM>>>(
        x, (const char*)whp, (const char*)wlp, qkv_b, (float*)qkv_ptr);
    // 3. attention
    attn_hmma_kernel<<<dim3(BATCH, HEADS), 256, ATTN_SMEM>>>();
    // 4. output projection
    gemm_hmma<1><<<MTOT / 64, 256, GEMM_SMEM>>>(
        (const float*)att_ptr, (const char*)whp + 3 * 32768, (const char*)wlp + 3 * 32768,
        proj_b, out);
}

// round 9
// speedup vs baseline: 2.0024x; 1.2070x over previous
#include <cuda_runtime.h>
#include <cuda_bf16.h>
#include <stdint.h>
#include <math.h>

#define BATCH 2048
#define NTOK 98
#define DIM 128
#define HEADS 4
#define NWIN 256
#define NN (NTOK * NTOK)   // 9604
#define MTOT (BATCH * NTOK)  // 200704

// Scratch (device globals)
__device__ float g_qkv[(size_t)MTOT * 384];                 // [m][s*128+h*32+d]
__device__ float g_att[(size_t)MTOT * 128];                 // [m][h*32+d]
__device__ __nv_bfloat16 g_sbm[(size_t)NWIN * HEADS * NN];  // bias+mask bf16
__device__ uint4 g_wfrag[16384];                            // W in MMA-fragment layout

// ===========================================================================
__device__ __forceinline__ uint32_t smem_u32(const void* p) {
    uint32_t a;
    asm("{ .reg .u64 t; cvta.to.shared.u64 t, %1; cvt.u32.u64 %0, t; }" : "=r"(a) : "l"(p));
    return a;
}
__device__ __forceinline__ void ldsm_x4(uint32_t* r, uint32_t addr) {
    asm volatile("ldmatrix.sync.aligned.m8n8.x4.shared.b16 {%0,%1,%2,%3}, [%4];"
                 : "=r"(r[0]), "=r"(r[1]), "=r"(r[2]), "=r"(r[3]) : "r"(addr));
}
__device__ __forceinline__ void ldsm_x2(uint32_t* r, uint32_t addr) {
    asm volatile("ldmatrix.sync.aligned.m8n8.x2.shared.b16 {%0,%1}, [%2];"
                 : "=r"(r[0]), "=r"(r[1]) : "r"(addr));
}
__device__ __forceinline__ void ldsm_x2t(uint32_t* r, uint32_t addr) {
    asm volatile("ldmatrix.sync.aligned.m8n8.x2.trans.shared.b16 {%0,%1}, [%2];"
                 : "=r"(r[0]), "=r"(r[1]) : "r"(addr));
}
__device__ __forceinline__ void mma_bf16(float* d, const uint32_t* a, const uint32_t* b) {
    asm volatile("mma.sync.aligned.m16n8k16.row.col.f32.bf16.bf16.f32 "
                 "{%0,%1,%2,%3}, {%4,%5,%6,%7}, {%8,%9}, {%0,%1,%2,%3};"
                 : "+f"(d[0]), "+f"(d[1]), "+f"(d[2]), "+f"(d[3])
                 : "r"(a[0]), "r"(a[1]), "r"(a[2]), "r"(a[3]), "r"(b[0]), "r"(b[1]));
}
__device__ __forceinline__ uint32_t packbf(float a, float b) {
    __nv_bfloat162 t = __float22bfloat162_rn(make_float2(a, b));
    return *(uint32_t*)&t;
}
__device__ __forceinline__ float lopart(float v) {
    return v - __bfloat162float(__float2bfloat16(v));
}
__device__ __forceinline__ void split4(float4 v, uint2& hi, uint2& lo) {
    __nv_bfloat16 hx = __float2bfloat16(v.x), hy = __float2bfloat16(v.y);
    __nv_bfloat16 hz = __float2bfloat16(v.z), hw = __float2bfloat16(v.w);
    __nv_bfloat162 h0 = __halves2bfloat162(hx, hy), h1 = __halves2bfloat162(hz, hw);
    hi.x = *(uint32_t*)&h0; hi.y = *(uint32_t*)&h1;
    lo.x = packbf(v.x - __bfloat162float(hx), v.y - __bfloat162float(hy));
    lo.y = packbf(v.z - __bfloat162float(hz), v.w - __bfloat162float(hw));
}
// swizzled smem address: 256B-pitch rows, XOR 16B-chunk by row&7
__device__ __forceinline__ uint32_t swz(uint32_t r, uint32_t cb) {
    return (r << 8) + (cb ^ ((r & 7) << 4));
}

// ===========================================================================
// bias+mask combine
// ===========================================================================
__global__ void build_sbm_kernel(const float* __restrict__ table,
                                 const int* __restrict__ rel,
                                 const float* __restrict__ mask) {
    int nm = blockIdx.x * 256 + threadIdx.x;
    int wh = blockIdx.y;
    if (nm < NN) {
        int w = wh >> 2, h = wh & 3;
        float v = table[rel[nm] * HEADS + h] + mask[(size_t)w * NN + nm];
        g_sbm[(size_t)wh * NN + nm] = __float2bfloat16(v);
    }
}

// ===========================================================================
// W pre-split into MMA B-fragment layout.
// Image index: ((tile*8 + kc)*16 + nblk)*32 + lane  -> uint4 {h0,h1,l0,l1}
//   n  = nblk*8 + (lane>>2)   (col within 128-tile)
//   k0 = kc*16 + (lane&3)*2
//   h0 = bf16x2{W[n][k0],W[n][k0+1]}, h1 = {W[n][k0+8],W[n][k0+9]}, lo same.
// Tiles 0..2 = qkv_w rows t*128.., tile 3 = proj_w.
// ===========================================================================
__global__ void split_w_kernel(const float* __restrict__ qkv_w,
                               const float* __restrict__ proj_w) {
    int idx = blockIdx.x * 256 + threadIdx.x;   // 16384
    int tile = idx >> 12;
    int rem = idx & 4095;
    int lane = rem & 31;
    int nblk = (rem >> 5) & 15;
    int kc = rem >> 9;
    int n = nblk * 8 + (lane >> 2);
    int k0 = kc * 16 + (lane & 3) * 2;
    const float* W = (tile < 3) ? qkv_w + (size_t)(tile * 128 + n) * 128
                                : proj_w + (size_t)n * 128;
    float2 a = *(const float2*)(W + k0);
    float2 b = *(const float2*)(W + k0 + 8);
    uint4 o;
    o.x = packbf(__bfloat162float(__float2bfloat16(a.x)),
                 __bfloat162float(__float2bfloat16(a.y)));
    // pack hi parts directly
    {
        __nv_bfloat162 h = __halves2bfloat162(__float2bfloat16(a.x), __float2bfloat16(a.y));
        o.x = *(uint32_t*)&h;
        __nv_bfloat162 h2 = __halves2bfloat162(__float2bfloat16(b.x), __float2bfloat16(b.y));
        o.y = *(uint32_t*)&h2;
    }
    o.z = packbf(lopart(a.x), lopart(a.y));
    o.w = packbf(lopart(b.x), lopart(b.y));
    g_wfrag[idx] = o;
}

// ===========================================================================
// HMMA GEMM: C[M][N] = A[M][128] @ W[N][128]^T + bias  (bf16 hi/lo 3-pass)
// Block: 64 M-rows; loops NITER tiles of 128 N-cols. A staged+split once in
// 32KB smem; W fragments read directly from L2-resident image (no W smem,
// no per-tile syncs). 256 threads, 8 warps 32x32, 3 CTAs/SM.
// ===========================================================================
template<int NITER>
__global__ __launch_bounds__(256, 3) void gemm_hmma(
    const float* __restrict__ Af, const uint4* __restrict__ Wfrag,
    const float* __restrict__ bias, float* __restrict__ Cf)
{
    __shared__ char sm[32768];
    const uint32_t smb = smem_u32(sm);
    const int tid = threadIdx.x;
    const int wid = tid >> 5, lane = tid & 31;
    const size_t m0 = (size_t)blockIdx.x * 64;
    const int N = NITER * 128;

    // ---- stage A (64 rows x 128 cols, fp32 -> hi/lo), once ----
#pragma unroll
    for (int i = 0; i < 8; i++) {
        int idx = tid + 256 * i;
        int r = idx >> 5;
        int c4 = (idx & 31) << 2;
        float4 v = *(const float4*)(Af + (m0 + r) * 128 + c4);
        uint2 hi, lo;
        split4(v, hi, lo);
        *(uint2*)(sm + swz(r, c4 * 2)) = hi;
        *(uint2*)(sm + 16384 + swz(r, c4 * 2)) = lo;
    }
    __syncthreads();

    const int wm = (wid & 1) * 32;
    const int wnb = (wid >> 1) * 4;          // n-block base (8-col units)
    const int rq = lane >> 2, cq = (lane & 3) * 2;

#pragma unroll 1
    for (int it = 0; it < NITER; it++) {
        const int n0 = it * 128;

        float acc[2][4][4];
#pragma unroll
        for (int mi = 0; mi < 2; mi++)
#pragma unroll
            for (int ni = 0; ni < 4; ni++)
#pragma unroll
                for (int c = 0; c < 4; c++) acc[mi][ni][c] = 0.f;

#pragma unroll
        for (int kc = 0; kc < 8; kc++) {
            uint32_t cb = (uint32_t)(kc * 32 + ((lane >> 4) & 1) * 16);
            uint32_t ah[2][4], al[2][4];
#pragma unroll
            for (int mi = 0; mi < 2; mi++) {
                uint32_t r = (uint32_t)(wm + mi * 16 + (lane & 15));
                ldsm_x4(ah[mi], smb + swz(r, cb));
                ldsm_x4(al[mi], smb + 16384 + swz(r, cb));
            }
            const uint4* wp = Wfrag + ((size_t)(it * 8 + kc) * 16 + wnb) * 32 + lane;
#pragma unroll
            for (int ni = 0; ni < 4; ni++) {
                uint4 w = wp[ni * 32];
                uint32_t B0[2] = {w.x, w.y};
                uint32_t Bl[2] = {w.z, w.w};
#pragma unroll
                for (int mi = 0; mi < 2; mi++) {
                    mma_bf16(acc[mi][ni], ah[mi], B0);
                    mma_bf16(acc[mi][ni], al[mi], B0);
                    mma_bf16(acc[mi][ni], ah[mi], Bl);
                }
            }
        }

        // ---- epilogue (fp32) ----
#pragma unroll
        for (int mi = 0; mi < 2; mi++) {
            size_t rA = m0 + wm + mi * 16 + rq;
            size_t rB = rA + 8;
#pragma unroll
            for (int ni = 0; ni < 4; ni++) {
                int col = n0 + wnb * 8 + ni * 8 + cq;
                float b0 = bias[col], b1 = bias[col + 1];
                *(float2*)(Cf + rA * N + col) =
                    make_float2(acc[mi][ni][0] + b0, acc[mi][ni][1] + b1);
                *(float2*)(Cf + rB * N + col) =
                    make_float2(acc[mi][ni][2] + b0, acc[mi][ni][3] + b1);
            }
        }
    }
}

// ===========================================================================
// HMMA attention: one CTA per (window, head), 256 threads (8 warps x 16 rows).
// ===========================================================================
#define PITCH 80
#define QH_OFF 0
#define QL_OFF 10240
#define KH_OFF 20480
#define KL_OFF 29440
#define VH_OFF 38400
#define VL_OFF 47360
#define ATTN_SMEM 56320

__global__ __launch_bounds__(256, 3) void attn_hmma_kernel() {
    extern __shared__ char smraw[];
    const uint32_t smb = smem_u32(smraw);
    char* sm = smraw;

    const int b = blockIdx.x, h = blockIdx.y;
    const int tid = threadIdx.x;
    const int wid = tid >> 5, lane = tid & 31;

    // ---- zero only pad rows (98..111) of all 6 tiles ----
    {
        uint4 z = make_uint4(0, 0, 0, 0);
        for (int idx = tid; idx < 420; idx += 256) {
            int t = idx / 70;
            int rem = idx - t * 70;
            int row = 98 + rem / 5;
            int ch = rem % 5;
            uint32_t base = (t < 2) ? (uint32_t)(t * 10240)
                                    : (uint32_t)(20480 + (t - 2) * 8960);
            *(uint4*)(sm + base + row * PITCH + ch * 16) = z;
        }
    }
    __syncthreads();

    // ---- load Q (scaled) / K / V, split hi/lo bf16, pitch-80 rows ----
    const float scale = 0.17677669529663687f;
    const float* qg = g_qkv + ((size_t)b * NTOK) * 384 + h * 32;
    for (int idx = tid; idx < NTOK * 8; idx += 256) {
        int n = idx >> 3, c4 = (idx & 7) << 2;
        const float* src = qg + (size_t)n * 384 + c4;
        uint32_t off = (uint32_t)(n * PITCH + c4 * 2);
        uint2 hi, lo;

        float4 q = *(const float4*)src;
        q.x *= scale; q.y *= scale; q.z *= scale; q.w *= scale;
        split4(q, hi, lo);
        *(uint2*)(sm + QH_OFF + off) = hi;
        *(uint2*)(sm + QL_OFF + off) = lo;

        split4(*(const float4*)(src + 128), hi, lo);
        *(uint2*)(sm + KH_OFF + off) = hi;
        *(uint2*)(sm + KL_OFF + off) = lo;

        split4(*(const float4*)(src + 256), hi, lo);
        *(uint2*)(sm + VH_OFF + off) = hi;
        *(uint2*)(sm + VL_OFF + off) = lo;
    }
    __syncthreads();

    if (wid == 7) return;   // rows 112..127 are pure padding

    const int l8 = lane & 7;
    const int rq = lane >> 2;
    const int cq = (lane & 3) * 2;

    // ---- S = QK^T, 3 passes; warp owns rows [16*wid, 16*wid+16) ----
    float acc[13][4];
#pragma unroll
    for (int nt = 0; nt < 13; nt++)
#pragma unroll
        for (int c = 0; c < 4; c++) acc[nt][c] = 0.f;

    uint32_t qbase[3] = {smb + QH_OFF, smb + QH_OFF, smb + QL_OFF};
    uint32_t kbase[3] = {smb + KH_OFF, smb + KL_OFF, smb + KH_OFF};

#pragma unroll 1
    for (int p = 0; p < 3; p++) {
        uint32_t qb = qbase[p], kb = kbase[p];
#pragma unroll
        for (int kc = 0; kc < 2; kc++) {
            uint32_t r = (uint32_t)(wid * 16 + (lane & 15));
            uint32_t aoff = (uint32_t)(kc * 32 + ((lane >> 4) & 1) * 16);
            uint32_t a[4];
            ldsm_x4(a, qb + r * PITCH + aoff);
            uint32_t boff = (uint32_t)(kc * 32 + ((lane >> 3) & 1) * 16);
#pragma unroll
            for (int nt = 0; nt < 13; nt++) {
                uint32_t bf[2];
                ldsm_x2(bf, kb + (uint32_t)(nt * 8 + l8) * PITCH + boff);
                mma_bf16(acc[nt], a, bf);
            }
        }
    }

    // ---- bias+mask add (direct from gmem), softmax ----
    const __nv_bfloat16* sbm = g_sbm + ((size_t)((b & (NWIN - 1)) * HEADS + h)) * NN;
    const int rA = wid * 16 + rq;
    const int rB = rA + 8;
    float mxA = -1e30f, mxB = -1e30f;
#pragma unroll
    for (int nt = 0; nt < 13; nt++) {
        int col = nt * 8 + cq;
        if (col < 98) {
            if (rA < 98) {
                uint32_t u = __ldg((const uint32_t*)(sbm + rA * 98 + col));
                __nv_bfloat162 bb = *(__nv_bfloat162*)&u;
                acc[nt][0] += __bfloat162float(bb.x);
                acc[nt][1] += __bfloat162float(bb.y);
            }
            if (rB < 98) {
                uint32_t u = __ldg((const uint32_t*)(sbm + rB * 98 + col));
                __nv_bfloat162 bb = *(__nv_bfloat162*)&u;
                acc[nt][2] += __bfloat162float(bb.x);
                acc[nt][3] += __bfloat162float(bb.y);
            }
        } else {
            acc[nt][0] = -1e30f; acc[nt][1] = -1e30f;
            acc[nt][2] = -1e30f; acc[nt][3] = -1e30f;
        }
        mxA = fmaxf(mxA, fmaxf(acc[nt][0], acc[nt][1]));
        mxB = fmaxf(mxB, fmaxf(acc[nt][2], acc[nt][3]));
    }
    mxA = fmaxf(mxA, __shfl_xor_sync(0xffffffffu, mxA, 1));
    mxA = fmaxf(mxA, __shfl_xor_sync(0xffffffffu, mxA, 2));
    mxB = fmaxf(mxB, __shfl_xor_sync(0xffffffffu, mxB, 1));
    mxB = fmaxf(mxB, __shfl_xor_sync(0xffffffffu, mxB, 2));
    float sA = 0.f, sB = 0.f;
#pragma unroll
    for (int nt = 0; nt < 13; nt++) {
        float e0 = __expf(acc[nt][0] - mxA);
        float e1 = __expf(acc[nt][1] - mxA);
        float e2 = __expf(acc[nt][2] - mxB);
        float e3 = __expf(acc[nt][3] - mxB);
        acc[nt][0] = e0; acc[nt][1] = e1;
        acc[nt][2] = e2; acc[nt][3] = e3;
        sA += e0 + e1; sB += e2 + e3;
    }
    sA += __shfl_xor_sync(0xffffffffu, sA, 1);
    sA += __shfl_xor_sync(0xffffffffu, sA, 2);
    sB += __shfl_xor_sync(0xffffffffu, sB, 1);
    sB += __shfl_xor_sync(0xffffffffu, sB, 2);

    // ---- O = P V, 3 passes ----
    float oacc[4][4];
#pragma unroll
    for (int nh = 0; nh < 4; nh++)
#pragma unroll
        for (int c = 0; c < 4; c++) oacc[nh][c] = 0.f;

    uint32_t vbase[3] = {smb + VH_OFF, smb + VL_OFF, smb + VH_OFF};

#pragma unroll 1
    for (int p = 0; p < 3; p++) {
        uint32_t vb = vbase[p];
        bool lo = (p == 2);
#pragma unroll
        for (int kc = 0; kc < 7; kc++) {
            int nt0 = 2 * kc, nt1 = nt0 + 1;
            float v0 = acc[nt0][0], v1 = acc[nt0][1];
            float v2 = acc[nt0][2], v3 = acc[nt0][3];
            float w0 = 0.f, w1 = 0.f, w2 = 0.f, w3 = 0.f;
            if (nt1 < 13) {
                w0 = acc[nt1][0]; w1 = acc[nt1][1];
                w2 = acc[nt1][2]; w3 = acc[nt1][3];
            }
            if (lo) {
                v0 = lopart(v0); v1 = lopart(v1); v2 = lopart(v2); v3 = lopart(v3);
                w0 = lopart(w0); w1 = lopart(w1); w2 = lopart(w2); w3 = lopart(w3);
            }
            uint32_t amat[4];
            amat[0] = packbf(v0, v1);
            amat[1] = packbf(v2, v3);
            amat[2] = packbf(w0, w1);
            amat[3] = packbf(w2, w3);
            uint32_t vrow = (uint32_t)(kc * 16 + ((lane >> 3) & 1) * 8 + l8);
#pragma unroll
            for (int nh = 0; nh < 4; nh++) {
                uint32_t bf[2];
                ldsm_x2t(bf, vb + vrow * PITCH + nh * 16);
                mma_bf16(oacc[nh], amat, bf);
            }
        }
    }

    // ---- epilogue ----
    float invA = 1.0f / sA;
    float invB = 1.0f / sB;
#pragma unroll
    for (int nh = 0; nh < 4; nh++) {
        int col = nh * 8 + cq;
        if (rA < 98) {
            float2 o = make_float2(oacc[nh][0] * invA, oacc[nh][1] * invA);
            *(float2*)(g_att + ((size_t)b * NTOK + rA) * 128 + h * 32 + col) = o;
        }
        if (rB < 98) {
            float2 o = make_float2(oacc[nh][2] * invB, oacc[nh][3] * invB);
            *(float2*)(g_att + ((size_t)b * NTOK + rB) * 128 + h * 32 + col) = o;
        }
    }
}

// ===========================================================================
extern "C" void kernel_launch(void* const* d_in, const int* in_sizes, int n_in,
                              void* d_out, int out_size) {
    const float* x          = (const float*)d_in[0];
    const float* mask       = (const float*)d_in[1];
    const float* qkv_w      = (const float*)d_in[2];
    const float* qkv_b      = (const float*)d_in[3];
    const float* proj_w     = (const float*)d_in[4];
    const float* proj_b     = (const float*)d_in[5];
    const float* bias_table = (const float*)d_in[6];
    const int*   rel_index  = (const int*)d_in[7];
    float* out = (float*)d_out;

    void *qkv_ptr, *att_ptr, *wfp;
    cudaGetSymbolAddress(&qkv_ptr, g_qkv);
    cudaGetSymbolAddress(&att_ptr, g_att);
    cudaGetSymbolAddress(&wfp, g_wfrag);

    cudaFuncSetAttribute(attn_hmma_kernel,
                         cudaFuncAttributeMaxDynamicSharedMemorySize, ATTN_SMEM);

    // 1. prep: bias+mask combine + W fragment image
    build_sbm_kernel<<<dim3((NN + 255) / 256, NWIN * HEADS), 256>>>(bias_table, rel_index, mask);
    split_w_kernel<<<64, 256>>>(qkv_w, proj_w);
    // 2. QKV projection (3 N-tiles)
    gemm_hmma<3><<<MTOT / 64, 256>>>(x, (const uint4*)wfp, qkv_b, (float*)qkv_ptr);
    // 3. attention
    attn_hmma_kernel<<<dim3(BATCH, HEADS), 256, ATTN_SMEM>>>();
    // 4. output projection (tile 3 of the fragment image)
    gemm_hmma<1><<<MTOT / 64, 256>>>(
        (const float*)att_ptr, (const uint4*)wfp + 12288, proj_b, out);
}